// round 5
// baseline (speedup 1.0000x reference)
#include <cuda_runtime.h>
#include <mma.h>
using namespace nvcuda;

#define S     2048
#define H     16
#define D     64
#define HID   1024
#define KHH   204
#define LCOMP 512
#define KC    716     // KHH + LCOMP
#define KCPAD 768     // padded key count for attn2 chunking
#define SCALE 0.125f  // 1/sqrt(64)
#define NKT   16      // 128-wide k tiles per score row
#define LOG1EM8 -18.420680743952367f

// ---------------- device scratch (allocation-free; module globals) ----------------
__device__ float g_q[S * HID];
__device__ float g_k[S * HID];
__device__ float g_v[S * HID];
__device__ float g_ao[S * HID];
__device__ float g_scores[(size_t)H * S * S];   // scaled scores (256 MB)
__device__ float g_pm[H * S * NKT];             // per-tile row max
__device__ float g_pz[H * S * NKT];             // per-tile row sumexp
__device__ float g_rowM[H * S];
__device__ float g_rowZ[H * S];                 // 1/Z
__device__ float g_logZ[H * S];
__device__ float g_ent[H * S];                  // accumulates sum p*log(clip(p)) = -entropy
__device__ float g_maxa[H * S];
__device__ float g_infl[H * S];
__device__ float g_imp[S];
__device__ int   g_hhidx[KHH];
__device__ float g_kcat[(size_t)H * KCPAD * D];
__device__ float g_vcat[(size_t)H * KCPAD * D];

// ---------------- tf32 split helpers ----------------
__device__ __forceinline__ float tf32_rd(float x) {
    unsigned u;
    asm("cvt.rna.tf32.f32 %0, %1;" : "=r"(u) : "f"(x));
    return __uint_as_float(u);
}
__device__ __forceinline__ void tf32_split(float x, float& h, float& l) {
    h = tf32_rd(x);
    l = tf32_rd(x - h);
}

// ---------------- TF32x3 GEMM: 128x128x16 block, 8 warps @ 32x64 ----------------
// A row-major M x K (lda), B row-major K x N (ldb), C row-major (ldc)
__device__ __forceinline__ void gemm_tf32_body(const float* __restrict__ A,
                                               const float* __restrict__ B,
                                               float* __restrict__ C,
                                               int lda, int ldb, int ldc, int Kdim) {
    __shared__ float Ah[128][20], Al[128][20];
    __shared__ float Bh[16][132], Bl[16][132];
    int tid = threadIdx.x;
    int wid = tid >> 5;
    int wm = wid >> 1;          // 0..3
    int wn = wid & 1;           // 0..1
    int crow = blockIdx.y * 128;
    int ccol = blockIdx.x * 128;
    int ar = tid >> 1, ac = (tid & 1) * 8;
    int br = tid >> 4, bc = (tid & 15) * 8;

    wmma::fragment<wmma::accumulator, 16, 16, 8, float> acc[2][4];
#pragma unroll
    for (int i = 0; i < 2; i++)
#pragma unroll
        for (int j = 0; j < 4; j++) wmma::fill_fragment(acc[i][j], 0.0f);

    for (int k0 = 0; k0 < Kdim; k0 += 16) {
        float4 a0 = *(const float4*)&A[(size_t)(crow + ar) * lda + k0 + ac];
        float4 a1 = *(const float4*)&A[(size_t)(crow + ar) * lda + k0 + ac + 4];
        tf32_split(a0.x, Ah[ar][ac + 0], Al[ar][ac + 0]);
        tf32_split(a0.y, Ah[ar][ac + 1], Al[ar][ac + 1]);
        tf32_split(a0.z, Ah[ar][ac + 2], Al[ar][ac + 2]);
        tf32_split(a0.w, Ah[ar][ac + 3], Al[ar][ac + 3]);
        tf32_split(a1.x, Ah[ar][ac + 4], Al[ar][ac + 4]);
        tf32_split(a1.y, Ah[ar][ac + 5], Al[ar][ac + 5]);
        tf32_split(a1.z, Ah[ar][ac + 6], Al[ar][ac + 6]);
        tf32_split(a1.w, Ah[ar][ac + 7], Al[ar][ac + 7]);
        float4 b0 = *(const float4*)&B[(size_t)(k0 + br) * ldb + ccol + bc];
        float4 b1 = *(const float4*)&B[(size_t)(k0 + br) * ldb + ccol + bc + 4];
        tf32_split(b0.x, Bh[br][bc + 0], Bl[br][bc + 0]);
        tf32_split(b0.y, Bh[br][bc + 1], Bl[br][bc + 1]);
        tf32_split(b0.z, Bh[br][bc + 2], Bl[br][bc + 2]);
        tf32_split(b0.w, Bh[br][bc + 3], Bl[br][bc + 3]);
        tf32_split(b1.x, Bh[br][bc + 4], Bl[br][bc + 4]);
        tf32_split(b1.y, Bh[br][bc + 5], Bl[br][bc + 5]);
        tf32_split(b1.z, Bh[br][bc + 6], Bl[br][bc + 6]);
        tf32_split(b1.w, Bh[br][bc + 7], Bl[br][bc + 7]);
        __syncthreads();
#pragma unroll
        for (int ks = 0; ks < 16; ks += 8) {
            wmma::fragment<wmma::matrix_a, 16, 16, 8, wmma::precision::tf32, wmma::row_major> fah[2], fal[2];
            wmma::fragment<wmma::matrix_b, 16, 16, 8, wmma::precision::tf32, wmma::row_major> fbh[4], fbl[4];
#pragma unroll
            for (int i = 0; i < 2; i++) {
                wmma::load_matrix_sync(fah[i], &Ah[wm * 32 + i * 16][ks], 20);
                wmma::load_matrix_sync(fal[i], &Al[wm * 32 + i * 16][ks], 20);
            }
#pragma unroll
            for (int j = 0; j < 4; j++) {
                wmma::load_matrix_sync(fbh[j], &Bh[ks][wn * 64 + j * 16], 132);
                wmma::load_matrix_sync(fbl[j], &Bl[ks][wn * 64 + j * 16], 132);
            }
#pragma unroll
            for (int i = 0; i < 2; i++)
#pragma unroll
                for (int j = 0; j < 4; j++) {
                    wmma::mma_sync(acc[i][j], fah[i], fbh[j], acc[i][j]);
                    wmma::mma_sync(acc[i][j], fah[i], fbl[j], acc[i][j]);
                    wmma::mma_sync(acc[i][j], fal[i], fbh[j], acc[i][j]);
                }
        }
        __syncthreads();
    }
#pragma unroll
    for (int i = 0; i < 2; i++)
#pragma unroll
        for (int j = 0; j < 4; j++)
            wmma::store_matrix_sync(&C[(size_t)(crow + wm * 32 + i * 16) * ldc +
                                       ccol + wn * 64 + j * 16],
                                    acc[i][j], ldc, wmma::mem_row_major);
}

__global__ __launch_bounds__(256) void qkv_kernel(const float* __restrict__ x,
                                                  const float* __restrict__ wq,
                                                  const float* __restrict__ wk,
                                                  const float* __restrict__ wv) {
    const float* B = blockIdx.z == 0 ? wq : (blockIdx.z == 1 ? wk : wv);
    float* C = blockIdx.z == 0 ? g_q : (blockIdx.z == 1 ? g_k : g_v);
    gemm_tf32_body(x, B, C, HID, HID, HID, HID);
}

__global__ __launch_bounds__(256) void out_kernel(const float* __restrict__ wo,
                                                  float* __restrict__ out) {
    gemm_tf32_body(g_ao, wo, out, HID, HID, HID, HID);
}

// ---------------- scores: TF32x3 Q@K^T (K=64) + partial row stats ----------------
__global__ __launch_bounds__(256) void scores_kernel() {
    __shared__ float Ah[128][20], Al[128][20];
    __shared__ float Bh[16][132], Bl[16][132];
    int h  = blockIdx.z;
    int q0 = blockIdx.y * 128;
    int k0 = blockIdx.x * 128;
    int tid = threadIdx.x;
    int wid = tid >> 5;
    int wm = wid >> 1, wn = wid & 1;
    int ar = tid >> 1, ac = (tid & 1) * 8;
    int btok = tid >> 1, bd = (tid & 1) * 8;
    const float* qb = g_q + h * D;
    const float* kb = g_k + h * D;

    wmma::fragment<wmma::accumulator, 16, 16, 8, float> acc[2][4];
#pragma unroll
    for (int i = 0; i < 2; i++)
#pragma unroll
        for (int j = 0; j < 4; j++) wmma::fill_fragment(acc[i][j], 0.0f);

    for (int c0 = 0; c0 < D; c0 += 16) {
        float4 a0 = *(const float4*)&qb[(size_t)(q0 + ar) * HID + c0 + ac];
        float4 a1 = *(const float4*)&qb[(size_t)(q0 + ar) * HID + c0 + ac + 4];
        tf32_split(a0.x, Ah[ar][ac + 0], Al[ar][ac + 0]);
        tf32_split(a0.y, Ah[ar][ac + 1], Al[ar][ac + 1]);
        tf32_split(a0.z, Ah[ar][ac + 2], Al[ar][ac + 2]);
        tf32_split(a0.w, Ah[ar][ac + 3], Al[ar][ac + 3]);
        tf32_split(a1.x, Ah[ar][ac + 4], Al[ar][ac + 4]);
        tf32_split(a1.y, Ah[ar][ac + 5], Al[ar][ac + 5]);
        tf32_split(a1.z, Ah[ar][ac + 6], Al[ar][ac + 6]);
        tf32_split(a1.w, Ah[ar][ac + 7], Al[ar][ac + 7]);
        // B = K^T: Bs[d][token]
        float4 k0v = *(const float4*)&kb[(size_t)(k0 + btok) * HID + c0 + bd];
        float4 k1v = *(const float4*)&kb[(size_t)(k0 + btok) * HID + c0 + bd + 4];
        tf32_split(k0v.x, Bh[bd + 0][btok], Bl[bd + 0][btok]);
        tf32_split(k0v.y, Bh[bd + 1][btok], Bl[bd + 1][btok]);
        tf32_split(k0v.z, Bh[bd + 2][btok], Bl[bd + 2][btok]);
        tf32_split(k0v.w, Bh[bd + 3][btok], Bl[bd + 3][btok]);
        tf32_split(k1v.x, Bh[bd + 4][btok], Bl[bd + 4][btok]);
        tf32_split(k1v.y, Bh[bd + 5][btok], Bl[bd + 5][btok]);
        tf32_split(k1v.z, Bh[bd + 6][btok], Bl[bd + 6][btok]);
        tf32_split(k1v.w, Bh[bd + 7][btok], Bl[bd + 7][btok]);
        __syncthreads();
#pragma unroll
        for (int ks = 0; ks < 16; ks += 8) {
            wmma::fragment<wmma::matrix_a, 16, 16, 8, wmma::precision::tf32, wmma::row_major> fah[2], fal[2];
            wmma::fragment<wmma::matrix_b, 16, 16, 8, wmma::precision::tf32, wmma::row_major> fbh[4], fbl[4];
#pragma unroll
            for (int i = 0; i < 2; i++) {
                wmma::load_matrix_sync(fah[i], &Ah[wm * 32 + i * 16][ks], 20);
                wmma::load_matrix_sync(fal[i], &Al[wm * 32 + i * 16][ks], 20);
            }
#pragma unroll
            for (int j = 0; j < 4; j++) {
                wmma::load_matrix_sync(fbh[j], &Bh[ks][wn * 64 + j * 16], 132);
                wmma::load_matrix_sync(fbl[j], &Bl[ks][wn * 64 + j * 16], 132);
            }
#pragma unroll
            for (int i = 0; i < 2; i++)
#pragma unroll
                for (int j = 0; j < 4; j++) {
                    wmma::mma_sync(acc[i][j], fah[i], fbh[j], acc[i][j]);
                    wmma::mma_sync(acc[i][j], fah[i], fbl[j], acc[i][j]);
                    wmma::mma_sync(acc[i][j], fal[i], fbh[j], acc[i][j]);
                }
        }
        __syncthreads();
    }
    float* sc = g_scores + (size_t)h * S * S;
#pragma unroll
    for (int i = 0; i < 2; i++)
#pragma unroll
        for (int j = 0; j < 4; j++) {
#pragma unroll
            for (int e = 0; e < acc[i][j].num_elements; e++) acc[i][j].x[e] *= SCALE;
            wmma::store_matrix_sync(&sc[(size_t)(q0 + wm * 32 + i * 16) * S +
                                        k0 + wn * 64 + j * 16],
                                    acc[i][j], S, wmma::mem_row_major);
        }
    __syncthreads();  // orders intra-block global writes before reads below

    // per-tile row stats over the 128-wide tile just written (L1/L2-hot)
    int lane = tid & 31;
#pragma unroll 4
    for (int r = 0; r < 16; r++) {
        int row = q0 + wid * 16 + r;
        float4 v = *(const float4*)&sc[(size_t)row * S + k0 + lane * 4];
        float m = fmaxf(fmaxf(v.x, v.y), fmaxf(v.z, v.w));
#pragma unroll
        for (int o = 16; o; o >>= 1) m = fmaxf(m, __shfl_xor_sync(0xffffffffu, m, o));
        float z = __expf(v.x - m) + __expf(v.y - m) + __expf(v.z - m) + __expf(v.w - m);
#pragma unroll
        for (int o = 16; o; o >>= 1) z += __shfl_xor_sync(0xffffffffu, z, o);
        if (lane == 0) {
            size_t idx = (size_t)(h * S + row) * NKT + blockIdx.x;
            g_pm[idx] = m;
            g_pz[idx] = z;
        }
    }
}

// ---------------- combine partials: m, 1/Z, logZ, max_attn ----------------
__global__ __launch_bounds__(256) void combine_kernel() {
    int row = blockIdx.x * 16 + (threadIdx.x >> 4);  // 0..H*S-1
    int l   = threadIdx.x & 15;
    float pm = g_pm[(size_t)row * NKT + l];
    float pz = g_pz[(size_t)row * NKT + l];
    float m = pm;
#pragma unroll
    for (int o = 1; o < 16; o <<= 1) m = fmaxf(m, __shfl_xor_sync(0xffffffffu, m, o));
    float z = __expf(pm - m) * pz;
#pragma unroll
    for (int o = 1; o < 16; o <<= 1) z += __shfl_xor_sync(0xffffffffu, z, o);
    if (l == 0) {
        float rz = 1.0f / z;
        g_rowM[row] = m;
        g_rowZ[row] = rz;
        g_logZ[row] = __logf(z);
        g_maxa[row] = rz;
    }
}

// ---------------- fused entropy + influence: single pass over scores ----------------
__global__ __launch_bounds__(256) void stats_kernel() {
    int h  = blockIdx.z;
    int q0 = blockIdx.y * 128;
    int k0 = blockIdx.x * 128;
    int tid = threadIdx.x;
    int wid = tid >> 5, lane = tid & 31;
    __shared__ float wcol[8][128];

    const float* sc = g_scores + (size_t)h * S * S;
    float c0 = 0.f, c1 = 0.f, c2 = 0.f, c3 = 0.f;

#pragma unroll 4
    for (int r = 0; r < 16; r++) {
        int row = q0 + wid * 16 + r;
        float m  = g_rowM[h * S + row];
        float rz = g_rowZ[h * S + row];
        float lz = g_logZ[h * S + row];
        float4 v = *(const float4*)&sc[(size_t)row * S + k0 + lane * 4];
        float s0 = v.x - m, s1 = v.y - m, s2 = v.z - m, s3 = v.w - m;
        float p0 = __expf(s0) * rz, p1 = __expf(s1) * rz;
        float p2 = __expf(s2) * rz, p3 = __expf(s3) * rz;
        c0 += p0; c1 += p1; c2 += p2; c3 += p3;
        float t0 = p0 * ((p0 >= 1e-8f) ? (s0 - lz) : LOG1EM8);
        float t1 = p1 * ((p1 >= 1e-8f) ? (s1 - lz) : LOG1EM8);
        float t2 = p2 * ((p2 >= 1e-8f) ? (s2 - lz) : LOG1EM8);
        float t3 = p3 * ((p3 >= 1e-8f) ? (s3 - lz) : LOG1EM8);
        float e = t0 + t1 + t2 + t3;
#pragma unroll
        for (int o = 16; o; o >>= 1) e += __shfl_xor_sync(0xffffffffu, e, o);
        if (lane == 0) atomicAdd(&g_ent[h * S + row], e);
    }
    *(float4*)&wcol[wid][lane * 4] = make_float4(c0, c1, c2, c3);
    __syncthreads();
    if (tid < 128) {
        float s = 0.f;
#pragma unroll
        for (int w = 0; w < 8; w++) s += wcol[w][tid];
        atomicAdd(&g_infl[h * S + k0 + tid], s);
    }
}

__global__ void importance_kernel() {
    int s = blockIdx.x * 256 + threadIdx.x;
    if (s >= S) return;
    float a = 0.f;
    for (int h = 0; h < H; h++)
        a += 0.4f * g_ent[h * S + s]   // g_ent = sum p log p = -entropy
           + 0.3f * g_maxa[h * S + s] + 0.3f * g_infl[h * S + s];
    g_imp[s] = a * (1.0f / H);
}

// ---------------- top-204 via rank counting ----------------
__global__ void topk_kernel() {
    int i = blockIdx.x * 256 + threadIdx.x;
    if (i >= S) return;
    float vi = g_imp[i];
    int r = 0;
    for (int j = 0; j < S; j++) {
        float vj = g_imp[j];
        r += (vj > vi) || (vj == vi && j < i);
    }
    if (r < KHH) g_hhidx[r] = i;
}

// ---------------- norm-softmax-weighted 4:1 compression of K/V ----------------
__global__ __launch_bounds__(256) void compress_kernel() {
    int h = blockIdx.x;
    int which = blockIdx.y;
    const float* src = which ? g_v : g_k;
    float* dst = (which ? g_vcat : g_kcat) + ((size_t)h * KCPAD + KHH) * D;
    __shared__ float w[S];
    __shared__ float gs[LCOMP];
    __shared__ float red[256];
    int tid = threadIdx.x;

    for (int s = tid; s < S; s += 256) {
        const float* rp = src + (size_t)s * HID + h * D;
        float a = 0.f;
#pragma unroll
        for (int dd = 0; dd < 64; dd += 4) {
            float4 xv = *(const float4*)&rp[dd];
            a += xv.x * xv.x + xv.y * xv.y + xv.z * xv.z + xv.w * xv.w;
        }
        w[s] = sqrtf(a);
    }
    __syncthreads();
    float lm = -1e30f;
    for (int s = tid; s < S; s += 256) lm = fmaxf(lm, w[s]);
    red[tid] = lm; __syncthreads();
    for (int o = 128; o; o >>= 1) { if (tid < o) red[tid] = fmaxf(red[tid], red[tid + o]); __syncthreads(); }
    float m = red[0]; __syncthreads();
    float lz = 0.f;
    for (int s = tid; s < S; s += 256) { float e = __expf(w[s] - m); w[s] = e; lz += e; }
    red[tid] = lz; __syncthreads();
    for (int o = 128; o; o >>= 1) { if (tid < o) red[tid] += red[tid + o]; __syncthreads(); }
    float rz = 1.0f / red[0]; __syncthreads();
    for (int s = tid; s < S; s += 256) w[s] *= rz;
    __syncthreads();
    for (int l = tid; l < LCOMP; l += 256)
        gs[l] = w[4 * l] + w[4 * l + 1] + w[4 * l + 2] + w[4 * l + 3];
    __syncthreads();
    for (int idx = tid; idx < LCOMP * D; idx += 256) {
        int l  = idx >> 6;
        int dd = idx & 63;
        const float* rp = src + (size_t)(4 * l) * HID + h * D + dd;
        float num = w[4 * l] * rp[0] + w[4 * l + 1] * rp[HID] +
                    w[4 * l + 2] * rp[2 * HID] + w[4 * l + 3] * rp[3 * HID];
        dst[(size_t)l * D + dd] = num / (gs[l] + 1e-8f);
    }
}

__global__ void gather_kernel() {
    int idx = blockIdx.x * 256 + threadIdx.x;
    if (idx >= H * KHH * D) return;
    int d = idx & 63;
    int i = (idx >> 6) % KHH;
    int h = idx / (KHH * D);
    int s = g_hhidx[i];
    g_kcat[((size_t)h * KCPAD + i) * D + d] = g_k[(size_t)s * HID + h * D + d];
    g_vcat[((size_t)h * KCPAD + i) * D + d] = g_v[(size_t)s * HID + h * D + d];
}

// ---------------- flash-style attention over 716(+pad) keys: 128 queries / block ----------------
__global__ __launch_bounds__(256) void attn2_kernel() {
    extern __shared__ float sm[];
    float* Qt  = sm;                       // [64][132]  Q^T  (d-major)
    float* KVs = sm + 64 * 132;            // [64][68]   K^T then V
    float* Pt  = sm + 64 * 132 + 64 * 68;  // [64][132]  P^T  (k-major)
    int h   = blockIdx.y;
    int q0  = blockIdx.x * 128;
    int tid = threadIdx.x;
    int tRow = (tid >> 4) * 8;   // q rows
    int tc4  = (tid & 15) * 4;   // k cols / d cols

    for (int f = tid; f < 128 * 16; f += 256) {
        int r = f >> 4, c = (f & 15) << 2;
        float4 qv = *(const float4*)&g_q[(size_t)(q0 + r) * HID + h * D + c];
        Qt[(c + 0) * 132 + r] = qv.x; Qt[(c + 1) * 132 + r] = qv.y;
        Qt[(c + 2) * 132 + r] = qv.z; Qt[(c + 3) * 132 + r] = qv.w;
    }
    const float* kbase = g_kcat + (size_t)h * KCPAD * D;
    const float* vbase = g_vcat + (size_t)h * KCPAD * D;

    float oc[8][4];
    float m_run[8], z_run[8];
#pragma unroll
    for (int i = 0; i < 8; i++) {
        m_run[i] = -1e30f; z_run[i] = 0.f;
#pragma unroll
        for (int j = 0; j < 4; j++) oc[i][j] = 0.f;
    }

    for (int kt = 0; kt < KCPAD; kt += 64) {
        __syncthreads();
        for (int f = tid; f < 64 * 16; f += 256) {
            int kr = f >> 4, c = (f & 15) << 2;
            float4 kv = *(const float4*)&kbase[(size_t)(kt + kr) * D + c];
            KVs[(c + 0) * 68 + kr] = kv.x; KVs[(c + 1) * 68 + kr] = kv.y;
            KVs[(c + 2) * 68 + kr] = kv.z; KVs[(c + 3) * 68 + kr] = kv.w;
        }
        __syncthreads();
        float s[8][4];
#pragma unroll
        for (int i = 0; i < 8; i++)
#pragma unroll
            for (int j = 0; j < 4; j++) s[i][j] = 0.f;
#pragma unroll 8
        for (int dd = 0; dd < 64; dd++) {
            float rm[8], rn[4];
            *(float4*)&rm[0] = *(float4*)&Qt[dd * 132 + tRow];
            *(float4*)&rm[4] = *(float4*)&Qt[dd * 132 + tRow + 4];
            *(float4*)&rn[0] = *(float4*)&KVs[dd * 68 + tc4];
#pragma unroll
            for (int i = 0; i < 8; i++)
#pragma unroll
                for (int j = 0; j < 4; j++) s[i][j] += rm[i] * rn[j];
        }
        bool mk[4];
#pragma unroll
        for (int j = 0; j < 4; j++) mk[j] = (kt + tc4 + j) >= KC;
#pragma unroll
        for (int i = 0; i < 8; i++) {
#pragma unroll
            for (int j = 0; j < 4; j++)
                s[i][j] = mk[j] ? -1e30f : s[i][j] * SCALE;
            float cm = fmaxf(fmaxf(s[i][0], s[i][1]), fmaxf(s[i][2], s[i][3]));
#pragma unroll
            for (int o = 1; o < 16; o <<= 1) cm = fmaxf(cm, __shfl_xor_sync(0xffffffffu, cm, o));
            float mn  = fmaxf(m_run[i], cm);
            float fac = __expf(m_run[i] - mn);
            float p0 = __expf(s[i][0] - mn), p1 = __expf(s[i][1] - mn);
            float p2 = __expf(s[i][2] - mn), p3 = __expf(s[i][3] - mn);
            float zs = p0 + p1 + p2 + p3;
#pragma unroll
            for (int o = 1; o < 16; o <<= 1) zs += __shfl_xor_sync(0xffffffffu, zs, o);
            z_run[i] = z_run[i] * fac + zs;
            m_run[i] = mn;
#pragma unroll
            for (int j = 0; j < 4; j++) oc[i][j] *= fac;
            Pt[(tc4 + 0) * 132 + tRow + i] = p0;
            Pt[(tc4 + 1) * 132 + tRow + i] = p1;
            Pt[(tc4 + 2) * 132 + tRow + i] = p2;
            Pt[(tc4 + 3) * 132 + tRow + i] = p3;
        }
        __syncthreads();
        for (int f = tid; f < 64 * 16; f += 256) {
            int kr = f >> 4, c = (f & 15) << 2;
            *(float4*)&KVs[kr * 68 + c] =
                *(const float4*)&vbase[(size_t)(kt + kr) * D + c];
        }
        __syncthreads();
#pragma unroll 8
        for (int kk = 0; kk < 64; kk++) {
            float rm[8], rn[4];
            *(float4*)&rm[0] = *(float4*)&Pt[kk * 132 + tRow];
            *(float4*)&rm[4] = *(float4*)&Pt[kk * 132 + tRow + 4];
            *(float4*)&rn[0] = *(float4*)&KVs[kk * 68 + tc4];
#pragma unroll
            for (int i = 0; i < 8; i++)
#pragma unroll
                for (int j = 0; j < 4; j++) oc[i][j] += rm[i] * rn[j];
        }
    }
#pragma unroll
    for (int i = 0; i < 8; i++) {
        float rz = 1.0f / z_run[i];
        *(float4*)&g_ao[(size_t)(q0 + tRow + i) * HID + h * D + tc4] =
            make_float4(oc[i][0] * rz, oc[i][1] * rz, oc[i][2] * rz, oc[i][3] * rz);
    }
}

// ---------------- host ----------------
#define ATTN2_SMEM ((64 * 132 + 64 * 68 + 64 * 132) * (int)sizeof(float))

extern "C" void kernel_launch(void* const* d_in, const int* in_sizes, int n_in,
                              void* d_out, int out_size) {
    const float* x  = (const float*)d_in[0];
    const float* wq = (const float*)d_in[1];
    const float* wk = (const float*)d_in[2];
    const float* wv = (const float*)d_in[3];
    const float* wo = (const float*)d_in[4];
    float* out = (float*)d_out;

    static bool init_done = false;
    static void* ent_addr = nullptr;
    static void* infl_addr = nullptr;
    static void* kcat_addr = nullptr;
    static void* vcat_addr = nullptr;
    if (!init_done) {
        cudaFuncSetAttribute(attn2_kernel,
                             cudaFuncAttributeMaxDynamicSharedMemorySize, ATTN2_SMEM);
        cudaGetSymbolAddress(&ent_addr, g_ent);
        cudaGetSymbolAddress(&infl_addr, g_infl);
        cudaGetSymbolAddress(&kcat_addr, g_kcat);
        cudaGetSymbolAddress(&vcat_addr, g_vcat);
        init_done = true;
    }

    cudaMemsetAsync(ent_addr, 0, H * S * sizeof(float));
    cudaMemsetAsync(infl_addr, 0, H * S * sizeof(float));
    cudaMemsetAsync(kcat_addr, 0, (size_t)H * KCPAD * D * sizeof(float));
    cudaMemsetAsync(vcat_addr, 0, (size_t)H * KCPAD * D * sizeof(float));

    qkv_kernel<<<dim3(8, 16, 3), 256>>>(x, wq, wk, wv);
    scores_kernel<<<dim3(16, 16, 16), 256>>>();
    combine_kernel<<<(H * S) / 16, 256>>>();
    stats_kernel<<<dim3(16, 16, 16), 256>>>();
    importance_kernel<<<8, 256>>>();
    topk_kernel<<<8, 256>>>();
    compress_kernel<<<dim3(16, 2), 256>>>();
    gather_kernel<<<(H * KHH * D + 255) / 256, 256>>>();
    attn2_kernel<<<dim3(S / 128, H), 256, ATTN2_SMEM>>>();
    out_kernel<<<dim3(8, 16), 256>>>(wo, out);
}

// round 7
// speedup vs baseline: 2.5629x; 2.5629x over previous
#include <cuda_runtime.h>
#include <cuda_bf16.h>
#include <cstdint>

#define S     2048
#define H     16
#define D     64
#define HID   1024
#define KHH   204
#define LCOMP 512
#define KC    716
#define KCPAD 768
#define SCALE 0.125f
#define NKT   64      // 32-wide k sub-tiles per score row
#define LOG1EM8 -18.420680743952367f

#define PA 72   // bf16 pitch, row-major [row][k<=64] tiles
#define PB 136  // bf16 pitch, row-major [k][n<=128] tiles

// ---------------- device scratch ----------------
__device__ float g_q[S * HID];
__device__ float g_k[S * HID];
__device__ float g_v[S * HID];
__device__ float g_ao[S * HID];
__device__ float g_scores[(size_t)H * S * S];
__device__ float g_pm[(size_t)H * S * NKT];
__device__ float g_pz[(size_t)H * S * NKT];
__device__ float g_rowM[H * S];
__device__ float g_rowZ[H * S];
__device__ float g_logZ[H * S];
__device__ float g_ent[H * S];
__device__ float g_maxa[H * S];
__device__ float g_infl[H * S];
__device__ float g_imp[S];
__device__ int   g_hhidx[KHH];
__device__ float g_kcat[(size_t)H * KCPAD * D];
__device__ float g_vcat[(size_t)H * KCPAD * D];

// ---------------- mma.sync helpers ----------------
__device__ __forceinline__ uint32_t smem_u32(const void* p) {
    uint32_t a;
    asm("{ .reg .u64 t; cvta.to.shared.u64 t, %1; cvt.u32.u64 %0, t; }" : "=r"(a) : "l"(p));
    return a;
}
__device__ __forceinline__ void ldmx4(uint32_t* r, uint32_t addr) {
    asm volatile("ldmatrix.sync.aligned.m8n8.x4.shared.b16 {%0,%1,%2,%3}, [%4];"
                 : "=r"(r[0]), "=r"(r[1]), "=r"(r[2]), "=r"(r[3]) : "r"(addr));
}
__device__ __forceinline__ void ldmx2(uint32_t* r, uint32_t addr) {
    asm volatile("ldmatrix.sync.aligned.m8n8.x2.shared.b16 {%0,%1}, [%2];"
                 : "=r"(r[0]), "=r"(r[1]) : "r"(addr));
}
__device__ __forceinline__ void ldmx2t(uint32_t* r, uint32_t addr) {
    asm volatile("ldmatrix.sync.aligned.m8n8.x2.trans.shared.b16 {%0,%1}, [%2];"
                 : "=r"(r[0]), "=r"(r[1]) : "r"(addr));
}
__device__ __forceinline__ void mma16816(float* d, const uint32_t* a, const uint32_t* b) {
    asm volatile("mma.sync.aligned.m16n8k16.row.col.f32.bf16.bf16.f32 "
                 "{%0,%1,%2,%3}, {%4,%5,%6,%7}, {%8,%9}, {%0,%1,%2,%3};"
                 : "+f"(d[0]), "+f"(d[1]), "+f"(d[2]), "+f"(d[3])
                 : "r"(a[0]), "r"(a[1]), "r"(a[2]), "r"(a[3]), "r"(b[0]), "r"(b[1]));
}
__device__ __forceinline__ void bsplit(float x, __nv_bfloat16& h, __nv_bfloat16& l) {
    h = __float2bfloat16(x);
    l = __float2bfloat16(x - __bfloat162float(h));
}
__device__ __forceinline__ uint32_t bpack(__nv_bfloat16 a, __nv_bfloat16 b) {
    __nv_bfloat162 p = __halves2bfloat162(a, b);
    return *(uint32_t*)&p;
}
// split a float4 into two packed uint2 (hi pair, lo pair)
__device__ __forceinline__ void split4(float4 v, uint2& hh, uint2& ll) {
    __nv_bfloat16 h0, h1, h2, h3, l0, l1, l2, l3;
    bsplit(v.x, h0, l0); bsplit(v.y, h1, l1);
    bsplit(v.z, h2, l2); bsplit(v.w, h3, l3);
    hh = make_uint2(bpack(h0, h1), bpack(h2, h3));
    ll = make_uint2(bpack(l0, l1), bpack(l2, l3));
}

// warp compute for one 64-K chunk: acc[mi][ni][4] += A(128x64) x B(64x128) warp slice
// BKN=true: B smem layout [k][n] pitch PB (ldmatrix.trans); false: [n][k] pitch PA
template <bool BKN>
__device__ __forceinline__ void mma_chunk(uint32_t ahB, uint32_t alB,
                                          uint32_t bhB, uint32_t blB,
                                          int wm, int wn, int lane,
                                          float acc[4][4][4]) {
#pragma unroll
    for (int ks = 0; ks < 4; ks++) {
        uint32_t bh[4][2], bl[4][2];
#pragma unroll
        for (int ni = 0; ni < 4; ni++) {
            uint32_t off;
            if (BKN)
                off = ((uint32_t)(ks * 16 + (lane & 7) + ((lane >> 3) & 1) * 8) * PB
                       + wn * 32 + ni * 8) * 2;
            else
                off = ((uint32_t)(wn * 32 + ni * 8 + (lane & 7)) * PA
                       + ks * 16 + ((lane >> 3) & 1) * 8) * 2;
            if (BKN) { ldmx2t(bh[ni], bhB + off); ldmx2t(bl[ni], blB + off); }
            else     { ldmx2 (bh[ni], bhB + off); ldmx2 (bl[ni], blB + off); }
        }
        uint32_t a[4][4];
        uint32_t aoff[4];
#pragma unroll
        for (int mi = 0; mi < 4; mi++) {
            aoff[mi] = ((uint32_t)(wm * 64 + mi * 16 + (lane & 15)) * PA
                        + ks * 16 + ((lane >> 4) << 3)) * 2;
            ldmx4(a[mi], ahB + aoff[mi]);
        }
#pragma unroll
        for (int mi = 0; mi < 4; mi++)
#pragma unroll
            for (int ni = 0; ni < 4; ni++) {
                mma16816(acc[mi][ni], a[mi], bh[ni]);
                mma16816(acc[mi][ni], a[mi], bl[ni]);
            }
#pragma unroll
        for (int mi = 0; mi < 4; mi++) ldmx4(a[mi], alB + aoff[mi]);
#pragma unroll
        for (int mi = 0; mi < 4; mi++)
#pragma unroll
            for (int ni = 0; ni < 4; ni++) mma16816(acc[mi][ni], a[mi], bh[ni]);
    }
}

#define GEMM_SMEM  (128 * PA * 2 * 2 + 64 * PB * 2 * 2)   // 71680
#define SCORE_SMEM (128 * PA * 2 * 4)                     // 73728

// ---------------- bf16x3 mma GEMM: C(128x128 tile) = A @ B, K = nch*64 ----------------
__device__ __forceinline__ void gemm_mma_body(const float* __restrict__ A,
                                              const float* __restrict__ Bm,
                                              float* __restrict__ C, int nch) {
    extern __shared__ char dsm[];
    char* Ah = dsm;
    char* Al = Ah + 128 * PA * 2;
    char* Bh = Al + 128 * PA * 2;
    char* Bl = Bh + 64 * PB * 2;
    uint32_t ahB = smem_u32(Ah), alB = smem_u32(Al);
    uint32_t bhB = smem_u32(Bh), blB = smem_u32(Bl);
    int tid = threadIdx.x;
    int wid = tid >> 5, lane = tid & 31;
    int wm = wid >> 2, wn = wid & 3;
    int crow = blockIdx.y * 128, ccol = blockIdx.x * 128;

    float acc[4][4][4];
#pragma unroll
    for (int mi = 0; mi < 4; mi++)
#pragma unroll
        for (int ni = 0; ni < 4; ni++)
#pragma unroll
            for (int e = 0; e < 4; e++) acc[mi][ni][e] = 0.f;

    for (int ch = 0; ch < nch; ch++) {
        int k0 = ch * 64;
        __syncthreads();
        // A tile: [row][k] pitch PA
#pragma unroll
        for (int i = 0; i < 8; i++) {
            int idx = tid + i * 256;
            int row = idx >> 4, c4 = (idx & 15) * 4;
            float4 v = *(const float4*)&A[(size_t)(crow + row) * HID + k0 + c4];
            uint2 hh, ll;
            split4(v, hh, ll);
            *(uint2*)(Ah + ((uint32_t)row * PA + c4) * 2) = hh;
            *(uint2*)(Al + ((uint32_t)row * PA + c4) * 2) = ll;
        }
        // B tile: [k][n] pitch PB (natural row-major copy)
#pragma unroll
        for (int i = 0; i < 8; i++) {
            int idx = tid + i * 256;
            int kr = idx >> 5, n4 = (idx & 31) * 4;
            float4 v = *(const float4*)&Bm[(size_t)(k0 + kr) * HID + ccol + n4];
            uint2 hh, ll;
            split4(v, hh, ll);
            *(uint2*)(Bh + ((uint32_t)kr * PB + n4) * 2) = hh;
            *(uint2*)(Bl + ((uint32_t)kr * PB + n4) * 2) = ll;
        }
        __syncthreads();
        mma_chunk<true>(ahB, alB, bhB, blB, wm, wn, lane, acc);
    }

    int quad = lane >> 2, ql = lane & 3;
#pragma unroll
    for (int mi = 0; mi < 4; mi++)
#pragma unroll
        for (int ni = 0; ni < 4; ni++) {
            int r = crow + wm * 64 + mi * 16 + quad;
            int c = ccol + wn * 32 + ni * 8 + ql * 2;
            *(float2*)&C[(size_t)r * HID + c] = make_float2(acc[mi][ni][0], acc[mi][ni][1]);
            *(float2*)&C[(size_t)(r + 8) * HID + c] = make_float2(acc[mi][ni][2], acc[mi][ni][3]);
        }
}

__global__ __launch_bounds__(256) void qkv_mma_kernel(const float* __restrict__ x,
                                                      const float* __restrict__ wq,
                                                      const float* __restrict__ wk,
                                                      const float* __restrict__ wv) {
    const float* B = blockIdx.z == 0 ? wq : (blockIdx.z == 1 ? wk : wv);
    float* C = blockIdx.z == 0 ? g_q : (blockIdx.z == 1 ? g_k : g_v);
    gemm_mma_body(x, B, C, 16);
}

__global__ __launch_bounds__(256) void out_mma_kernel(const float* __restrict__ wo,
                                                      float* __restrict__ out) {
    gemm_mma_body(g_ao, wo, out, 16);
}

// ---------------- scores: bf16x3 mma Q@K^T (K=64) + fused row-stat partials ----------------
__global__ __launch_bounds__(256) void scores_mma_kernel() {
    extern __shared__ char dsm[];
    char* Ah = dsm;                  // Q [q][d] pitch PA
    char* Al = Ah + 128 * PA * 2;
    char* Bh = Al + 128 * PA * 2;    // K [tok][d] pitch PA  (B = [n][k] layout)
    char* Bl = Bh + 128 * PA * 2;
    uint32_t ahB = smem_u32(Ah), alB = smem_u32(Al);
    uint32_t bhB = smem_u32(Bh), blB = smem_u32(Bl);
    int tid = threadIdx.x;
    int wid = tid >> 5, lane = tid & 31;
    int wm = wid >> 2, wn = wid & 3;
    int h = blockIdx.z, q0 = blockIdx.y * 128, k0 = blockIdx.x * 128;
    const float* Aq = g_q + h * D;
    const float* Bk = g_k + h * D;

#pragma unroll
    for (int i = 0; i < 8; i++) {
        int idx = tid + i * 256;
        int row = idx >> 4, c4 = (idx & 15) * 4;
        uint32_t so = ((uint32_t)row * PA + c4) * 2;
        uint2 hh, ll;
        split4(*(const float4*)&Aq[(size_t)(q0 + row) * HID + c4], hh, ll);
        *(uint2*)(Ah + so) = hh;
        *(uint2*)(Al + so) = ll;
        split4(*(const float4*)&Bk[(size_t)(k0 + row) * HID + c4], hh, ll);
        *(uint2*)(Bh + so) = hh;
        *(uint2*)(Bl + so) = ll;
    }
    __syncthreads();

    float acc[4][4][4];
#pragma unroll
    for (int mi = 0; mi < 4; mi++)
#pragma unroll
        for (int ni = 0; ni < 4; ni++)
#pragma unroll
            for (int e = 0; e < 4; e++) acc[mi][ni][e] = 0.f;

    mma_chunk<false>(ahB, alB, bhB, blB, wm, wn, lane, acc);

    // scale + store + per-32col row stats
#pragma unroll
    for (int mi = 0; mi < 4; mi++)
#pragma unroll
        for (int ni = 0; ni < 4; ni++)
#pragma unroll
            for (int e = 0; e < 4; e++) acc[mi][ni][e] *= SCALE;

    float* sc = g_scores + (size_t)h * S * S;
    int quad = lane >> 2, ql = lane & 3;
#pragma unroll
    for (int mi = 0; mi < 4; mi++)
#pragma unroll
        for (int ni = 0; ni < 4; ni++) {
            int r = q0 + wm * 64 + mi * 16 + quad;
            int c = k0 + wn * 32 + ni * 8 + ql * 2;
            *(float2*)&sc[(size_t)r * S + c] = make_float2(acc[mi][ni][0], acc[mi][ni][1]);
            *(float2*)&sc[(size_t)(r + 8) * S + c] = make_float2(acc[mi][ni][2], acc[mi][ni][3]);
        }

    // row stats: each quad owns 2 rows (r, r+8) per mi, 32 cols per warp
    int tile = blockIdx.x * 4 + wn;
#pragma unroll
    for (int mi = 0; mi < 4; mi++) {
        float m0 = -1e30f, m1 = -1e30f;
#pragma unroll
        for (int ni = 0; ni < 4; ni++) {
            m0 = fmaxf(m0, fmaxf(acc[mi][ni][0], acc[mi][ni][1]));
            m1 = fmaxf(m1, fmaxf(acc[mi][ni][2], acc[mi][ni][3]));
        }
        m0 = fmaxf(m0, __shfl_xor_sync(0xffffffffu, m0, 1));
        m0 = fmaxf(m0, __shfl_xor_sync(0xffffffffu, m0, 2));
        m1 = fmaxf(m1, __shfl_xor_sync(0xffffffffu, m1, 1));
        m1 = fmaxf(m1, __shfl_xor_sync(0xffffffffu, m1, 2));
        float z0 = 0.f, z1 = 0.f;
#pragma unroll
        for (int ni = 0; ni < 4; ni++) {
            z0 += __expf(acc[mi][ni][0] - m0) + __expf(acc[mi][ni][1] - m0);
            z1 += __expf(acc[mi][ni][2] - m1) + __expf(acc[mi][ni][3] - m1);
        }
        z0 += __shfl_xor_sync(0xffffffffu, z0, 1);
        z0 += __shfl_xor_sync(0xffffffffu, z0, 2);
        z1 += __shfl_xor_sync(0xffffffffu, z1, 1);
        z1 += __shfl_xor_sync(0xffffffffu, z1, 2);
        if (ql == 0) {
            int r = q0 + wm * 64 + mi * 16 + quad;
            size_t p0 = (size_t)(h * S + r) * NKT + tile;
            size_t p1 = (size_t)(h * S + r + 8) * NKT + tile;
            g_pm[p0] = m0; g_pz[p0] = z0;
            g_pm[p1] = m1; g_pz[p1] = z1;
        }
    }
}

// ---------------- combine partials (64 per row) ----------------
__global__ __launch_bounds__(256) void combine_kernel() {
    int row  = blockIdx.x * 8 + (threadIdx.x >> 5);
    int lane = threadIdx.x & 31;
    float pm0 = g_pm[(size_t)row * NKT + lane];
    float pz0 = g_pz[(size_t)row * NKT + lane];
    float pm1 = g_pm[(size_t)row * NKT + 32 + lane];
    float pz1 = g_pz[(size_t)row * NKT + 32 + lane];
    float m = fmaxf(pm0, pm1);
#pragma unroll
    for (int o = 16; o; o >>= 1) m = fmaxf(m, __shfl_xor_sync(0xffffffffu, m, o));
    float z = __expf(pm0 - m) * pz0 + __expf(pm1 - m) * pz1;
#pragma unroll
    for (int o = 16; o; o >>= 1) z += __shfl_xor_sync(0xffffffffu, z, o);
    if (lane == 0) {
        float rz = 1.0f / z;
        g_rowM[row] = m;
        g_rowZ[row] = rz;
        g_logZ[row] = __logf(z);
        g_maxa[row] = rz;
    }
}

// ---------------- fused entropy + influence ----------------
__global__ __launch_bounds__(256) void stats_kernel() {
    int h  = blockIdx.z;
    int q0 = blockIdx.y * 128;
    int k0 = blockIdx.x * 128;
    int tid = threadIdx.x;
    int wid = tid >> 5, lane = tid & 31;
    __shared__ float wcol[8][128];

    const float* sc = g_scores + (size_t)h * S * S;
    float c0 = 0.f, c1 = 0.f, c2 = 0.f, c3 = 0.f;

#pragma unroll 4
    for (int r = 0; r < 16; r++) {
        int row = q0 + wid * 16 + r;
        float m  = g_rowM[h * S + row];
        float rz = g_rowZ[h * S + row];
        float lz = g_logZ[h * S + row];
        float4 v = *(const float4*)&sc[(size_t)row * S + k0 + lane * 4];
        float s0 = v.x - m, s1 = v.y - m, s2 = v.z - m, s3 = v.w - m;
        float p0 = __expf(s0) * rz, p1 = __expf(s1) * rz;
        float p2 = __expf(s2) * rz, p3 = __expf(s3) * rz;
        c0 += p0; c1 += p1; c2 += p2; c3 += p3;
        float t0 = p0 * ((p0 >= 1e-8f) ? (s0 - lz) : LOG1EM8);
        float t1 = p1 * ((p1 >= 1e-8f) ? (s1 - lz) : LOG1EM8);
        float t2 = p2 * ((p2 >= 1e-8f) ? (s2 - lz) : LOG1EM8);
        float t3 = p3 * ((p3 >= 1e-8f) ? (s3 - lz) : LOG1EM8);
        float e = t0 + t1 + t2 + t3;
#pragma unroll
        for (int o = 16; o; o >>= 1) e += __shfl_xor_sync(0xffffffffu, e, o);
        if (lane == 0) atomicAdd(&g_ent[h * S + row], e);
    }
    *(float4*)&wcol[wid][lane * 4] = make_float4(c0, c1, c2, c3);
    __syncthreads();
    if (tid < 128) {
        float s = 0.f;
#pragma unroll
        for (int w = 0; w < 8; w++) s += wcol[w][tid];
        atomicAdd(&g_infl[h * S + k0 + tid], s);
    }
}

__global__ void importance_kernel() {
    int s = blockIdx.x * 256 + threadIdx.x;
    if (s >= S) return;
    float a = 0.f;
    for (int h = 0; h < H; h++)
        a += 0.4f * g_ent[h * S + s]
           + 0.3f * g_maxa[h * S + s] + 0.3f * g_infl[h * S + s];
    g_imp[s] = a * (1.0f / H);
}

__global__ void topk_kernel() {
    int i = blockIdx.x * 256 + threadIdx.x;
    if (i >= S) return;
    float vi = g_imp[i];
    int r = 0;
    for (int j = 0; j < S; j++) {
        float vj = g_imp[j];
        r += (vj > vi) || (vj == vi && j < i);
    }
    if (r < KHH) g_hhidx[r] = i;
}

// ---------------- norm-softmax-weighted 4:1 compression ----------------
__global__ __launch_bounds__(256) void compress_kernel() {
    int h = blockIdx.x;
    int which = blockIdx.y;
    const float* src = which ? g_v : g_k;
    float* dst = (which ? g_vcat : g_kcat) + ((size_t)h * KCPAD + KHH) * D;
    __shared__ float w[S];
    __shared__ float gs[LCOMP];
    __shared__ float red[256];
    int tid = threadIdx.x;

    for (int s = tid; s < S; s += 256) {
        const float* rp = src + (size_t)s * HID + h * D;
        float a = 0.f;
#pragma unroll
        for (int dd = 0; dd < 64; dd += 4) {
            float4 xv = *(const float4*)&rp[dd];
            a += xv.x * xv.x + xv.y * xv.y + xv.z * xv.z + xv.w * xv.w;
        }
        w[s] = sqrtf(a);
    }
    __syncthreads();
    float lm = -1e30f;
    for (int s = tid; s < S; s += 256) lm = fmaxf(lm, w[s]);
    red[tid] = lm; __syncthreads();
    for (int o = 128; o; o >>= 1) { if (tid < o) red[tid] = fmaxf(red[tid], red[tid + o]); __syncthreads(); }
    float m = red[0]; __syncthreads();
    float lz = 0.f;
    for (int s = tid; s < S; s += 256) { float e = __expf(w[s] - m); w[s] = e; lz += e; }
    red[tid] = lz; __syncthreads();
    for (int o = 128; o; o >>= 1) { if (tid < o) red[tid] += red[tid + o]; __syncthreads(); }
    float rz = 1.0f / red[0]; __syncthreads();
    for (int s = tid; s < S; s += 256) w[s] *= rz;
    __syncthreads();
    for (int l = tid; l < LCOMP; l += 256)
        gs[l] = w[4 * l] + w[4 * l + 1] + w[4 * l + 2] + w[4 * l + 3];
    __syncthreads();
    for (int idx = tid; idx < LCOMP * D; idx += 256) {
        int l  = idx >> 6;
        int dd = idx & 63;
        const float* rp = src + (size_t)(4 * l) * HID + h * D + dd;
        float num = w[4 * l] * rp[0] + w[4 * l + 1] * rp[HID] +
                    w[4 * l + 2] * rp[2 * HID] + w[4 * l + 3] * rp[3 * HID];
        dst[(size_t)l * D + dd] = num / (gs[l] + 1e-8f);
    }
}

__global__ void gather_kernel() {
    int idx = blockIdx.x * 256 + threadIdx.x;
    if (idx >= H * KHH * D) return;
    int d = idx & 63;
    int i = (idx >> 6) % KHH;
    int h = idx / (KHH * D);
    int s = g_hhidx[i];
    g_kcat[((size_t)h * KCPAD + i) * D + d] = g_k[(size_t)s * HID + h * D + d];
    g_vcat[((size_t)h * KCPAD + i) * D + d] = g_v[(size_t)s * HID + h * D + d];
}

// ---------------- flash-style attention over 716(+pad) keys ----------------
__global__ __launch_bounds__(256) void attn2_kernel() {
    extern __shared__ float sm[];
    float* Qt  = sm;                       // [64][132]
    float* KVs = sm + 64 * 132;            // [64][68]
    float* Pt  = sm + 64 * 132 + 64 * 68;  // [64][132]
    int h   = blockIdx.y;
    int q0  = blockIdx.x * 128;
    int tid = threadIdx.x;
    int tRow = (tid >> 4) * 8;
    int tc4  = (tid & 15) * 4;

    for (int f = tid; f < 128 * 16; f += 256) {
        int r = f >> 4, c = (f & 15) << 2;
        float4 qv = *(const float4*)&g_q[(size_t)(q0 + r) * HID + h * D + c];
        Qt[(c + 0) * 132 + r] = qv.x; Qt[(c + 1) * 132 + r] = qv.y;
        Qt[(c + 2) * 132 + r] = qv.z; Qt[(c + 3) * 132 + r] = qv.w;
    }
    const float* kbase = g_kcat + (size_t)h * KCPAD * D;
    const float* vbase = g_vcat + (size_t)h * KCPAD * D;

    float oc[8][4];
    float m_run[8], z_run[8];
#pragma unroll
    for (int i = 0; i < 8; i++) {
        m_run[i] = -1e30f; z_run[i] = 0.f;
#pragma unroll
        for (int j = 0; j < 4; j++) oc[i][j] = 0.f;
    }

    for (int kt = 0; kt < KCPAD; kt += 64) {
        __syncthreads();
        for (int f = tid; f < 64 * 16; f += 256) {
            int kr = f >> 4, c = (f & 15) << 2;
            float4 kv = *(const float4*)&kbase[(size_t)(kt + kr) * D + c];
            KVs[(c + 0) * 68 + kr] = kv.x; KVs[(c + 1) * 68 + kr] = kv.y;
            KVs[(c + 2) * 68 + kr] = kv.z; KVs[(c + 3) * 68 + kr] = kv.w;
        }
        __syncthreads();
        float s[8][4];
#pragma unroll
        for (int i = 0; i < 8; i++)
#pragma unroll
            for (int j = 0; j < 4; j++) s[i][j] = 0.f;
#pragma unroll 8
        for (int dd = 0; dd < 64; dd++) {
            float rm[8], rn[4];
            *(float4*)&rm[0] = *(float4*)&Qt[dd * 132 + tRow];
            *(float4*)&rm[4] = *(float4*)&Qt[dd * 132 + tRow + 4];
            *(float4*)&rn[0] = *(float4*)&KVs[dd * 68 + tc4];
#pragma unroll
            for (int i = 0; i < 8; i++)
#pragma unroll
                for (int j = 0; j < 4; j++) s[i][j] += rm[i] * rn[j];
        }
        bool mk[4];
#pragma unroll
        for (int j = 0; j < 4; j++) mk[j] = (kt + tc4 + j) >= KC;
#pragma unroll
        for (int i = 0; i < 8; i++) {
#pragma unroll
            for (int j = 0; j < 4; j++)
                s[i][j] = mk[j] ? -1e30f : s[i][j] * SCALE;
            float cm = fmaxf(fmaxf(s[i][0], s[i][1]), fmaxf(s[i][2], s[i][3]));
#pragma unroll
            for (int o = 1; o < 16; o <<= 1) cm = fmaxf(cm, __shfl_xor_sync(0xffffffffu, cm, o));
            float mn  = fmaxf(m_run[i], cm);
            float fac = __expf(m_run[i] - mn);
            float p0 = __expf(s[i][0] - mn), p1 = __expf(s[i][1] - mn);
            float p2 = __expf(s[i][2] - mn), p3 = __expf(s[i][3] - mn);
            float zs = p0 + p1 + p2 + p3;
#pragma unroll
            for (int o = 1; o < 16; o <<= 1) zs += __shfl_xor_sync(0xffffffffu, zs, o);
            z_run[i] = z_run[i] * fac + zs;
            m_run[i] = mn;
#pragma unroll
            for (int j = 0; j < 4; j++) oc[i][j] *= fac;
            Pt[(tc4 + 0) * 132 + tRow + i] = p0;
            Pt[(tc4 + 1) * 132 + tRow + i] = p1;
            Pt[(tc4 + 2) * 132 + tRow + i] = p2;
            Pt[(tc4 + 3) * 132 + tRow + i] = p3;
        }
        __syncthreads();
        for (int f = tid; f < 64 * 16; f += 256) {
            int kr = f >> 4, c = (f & 15) << 2;
            *(float4*)&KVs[kr * 68 + c] =
                *(const float4*)&vbase[(size_t)(kt + kr) * D + c];
        }
        __syncthreads();
#pragma unroll 8
        for (int kk = 0; kk < 64; kk++) {
            float rm[8], rn[4];
            *(float4*)&rm[0] = *(float4*)&Pt[kk * 132 + tRow];
            *(float4*)&rm[4] = *(float4*)&Pt[kk * 132 + tRow + 4];
            *(float4*)&rn[0] = *(float4*)&KVs[kk * 68 + tc4];
#pragma unroll
            for (int i = 0; i < 8; i++)
#pragma unroll
                for (int j = 0; j < 4; j++) oc[i][j] += rm[i] * rn[j];
        }
    }
#pragma unroll
    for (int i = 0; i < 8; i++) {
        float rz = 1.0f / z_run[i];
        *(float4*)&g_ao[(size_t)(q0 + tRow + i) * HID + h * D + tc4] =
            make_float4(oc[i][0] * rz, oc[i][1] * rz, oc[i][2] * rz, oc[i][3] * rz);
    }
}

// ---------------- host ----------------
#define ATTN2_SMEM ((64 * 132 + 64 * 68 + 64 * 132) * (int)sizeof(float))

extern "C" void kernel_launch(void* const* d_in, const int* in_sizes, int n_in,
                              void* d_out, int out_size) {
    const float* x  = (const float*)d_in[0];
    const float* wq = (const float*)d_in[1];
    const float* wk = (const float*)d_in[2];
    const float* wv = (const float*)d_in[3];
    const float* wo = (const float*)d_in[4];
    float* out = (float*)d_out;

    static bool init_done = false;
    static void* ent_addr = nullptr;
    static void* infl_addr = nullptr;
    static void* kcat_addr = nullptr;
    static void* vcat_addr = nullptr;
    if (!init_done) {
        cudaFuncSetAttribute(attn2_kernel,
                             cudaFuncAttributeMaxDynamicSharedMemorySize, ATTN2_SMEM);
        cudaFuncSetAttribute(qkv_mma_kernel,
                             cudaFuncAttributeMaxDynamicSharedMemorySize, GEMM_SMEM);
        cudaFuncSetAttribute(out_mma_kernel,
                             cudaFuncAttributeMaxDynamicSharedMemorySize, GEMM_SMEM);
        cudaFuncSetAttribute(scores_mma_kernel,
                             cudaFuncAttributeMaxDynamicSharedMemorySize, SCORE_SMEM);
        cudaGetSymbolAddress(&ent_addr, g_ent);
        cudaGetSymbolAddress(&infl_addr, g_infl);
        cudaGetSymbolAddress(&kcat_addr, g_kcat);
        cudaGetSymbolAddress(&vcat_addr, g_vcat);
        init_done = true;
    }

    cudaMemsetAsync(ent_addr, 0, H * S * sizeof(float));
    cudaMemsetAsync(infl_addr, 0, H * S * sizeof(float));
    cudaMemsetAsync(kcat_addr, 0, (size_t)H * KCPAD * D * sizeof(float));
    cudaMemsetAsync(vcat_addr, 0, (size_t)H * KCPAD * D * sizeof(float));

    qkv_mma_kernel<<<dim3(8, 16, 3), 256, GEMM_SMEM>>>(x, wq, wk, wv);
    scores_mma_kernel<<<dim3(16, 16, 16), 256, SCORE_SMEM>>>();
    combine_kernel<<<(H * S) / 8, 256>>>();
    stats_kernel<<<dim3(16, 16, 16), 256>>>();
    importance_kernel<<<8, 256>>>();
    topk_kernel<<<8, 256>>>();
    compress_kernel<<<dim3(16, 2), 256>>>();
    gather_kernel<<<(H * KHH * D + 255) / 256, 256>>>();
    attn2_kernel<<<dim3(S / 128, H), 256, ATTN2_SMEM>>>();
    out_mma_kernel<<<dim3(8, 16), 256, GEMM_SMEM>>>(wo, out);
}

// round 8
// speedup vs baseline: 3.1259x; 1.2197x over previous
#include <cuda_runtime.h>
#include <cuda_bf16.h>
#include <cstdint>

#define S     2048
#define H     16
#define D     64
#define HID   1024
#define KHH   204
#define LCOMP 512
#define KC    716
#define KCPAD 768
#define SCALE 0.125f
#define NKT   64      // 32-wide k sub-tiles per score row
#define LOG1EM8 -18.420680743952367f

#define PA 72   // bf16 pitch, row-major [row][k<=64] tiles
#define PB 136  // bf16 pitch, row-major [k][n<=128] tiles
#define PQ 72   // attn2 smem pitch

// ---------------- device scratch ----------------
__device__ float g_q[S * HID];
__device__ float g_k[S * HID];
__device__ float g_v[S * HID];
__device__ float g_ao[S * HID];
__device__ float g_scores[(size_t)H * S * S];
__device__ float g_pm[(size_t)H * S * NKT];
__device__ float g_pz[(size_t)H * S * NKT];
__device__ float g_rowM[H * S];
__device__ float g_rowZ[H * S];
__device__ float g_logZ[H * S];
__device__ float g_ent[H * S];
__device__ float g_maxa[H * S];
__device__ float g_infl[H * S];
__device__ float g_imp[S];
__device__ int   g_hhidx[KHH];
__device__ float g_kcat[(size_t)H * KCPAD * D];
__device__ float g_vcat[(size_t)H * KCPAD * D];

// ---------------- mma.sync helpers ----------------
__device__ __forceinline__ uint32_t smem_u32(const void* p) {
    uint32_t a;
    asm("{ .reg .u64 t; cvta.to.shared.u64 t, %1; cvt.u32.u64 %0, t; }" : "=r"(a) : "l"(p));
    return a;
}
__device__ __forceinline__ void ldmx4(uint32_t* r, uint32_t addr) {
    asm volatile("ldmatrix.sync.aligned.m8n8.x4.shared.b16 {%0,%1,%2,%3}, [%4];"
                 : "=r"(r[0]), "=r"(r[1]), "=r"(r[2]), "=r"(r[3]) : "r"(addr));
}
__device__ __forceinline__ void ldmx4t(uint32_t* r, uint32_t addr) {
    asm volatile("ldmatrix.sync.aligned.m8n8.x4.trans.shared.b16 {%0,%1,%2,%3}, [%4];"
                 : "=r"(r[0]), "=r"(r[1]), "=r"(r[2]), "=r"(r[3]) : "r"(addr));
}
__device__ __forceinline__ void ldmx2(uint32_t* r, uint32_t addr) {
    asm volatile("ldmatrix.sync.aligned.m8n8.x2.shared.b16 {%0,%1}, [%2];"
                 : "=r"(r[0]), "=r"(r[1]) : "r"(addr));
}
__device__ __forceinline__ void ldmx2t(uint32_t* r, uint32_t addr) {
    asm volatile("ldmatrix.sync.aligned.m8n8.x2.trans.shared.b16 {%0,%1}, [%2];"
                 : "=r"(r[0]), "=r"(r[1]) : "r"(addr));
}
__device__ __forceinline__ void mma16816(float* d, const uint32_t* a, const uint32_t* b) {
    asm volatile("mma.sync.aligned.m16n8k16.row.col.f32.bf16.bf16.f32 "
                 "{%0,%1,%2,%3}, {%4,%5,%6,%7}, {%8,%9}, {%0,%1,%2,%3};"
                 : "+f"(d[0]), "+f"(d[1]), "+f"(d[2]), "+f"(d[3])
                 : "r"(a[0]), "r"(a[1]), "r"(a[2]), "r"(a[3]), "r"(b[0]), "r"(b[1]));
}
__device__ __forceinline__ void bsplit(float x, __nv_bfloat16& h, __nv_bfloat16& l) {
    h = __float2bfloat16(x);
    l = __float2bfloat16(x - __bfloat162float(h));
}
__device__ __forceinline__ uint32_t bpack(__nv_bfloat16 a, __nv_bfloat16 b) {
    __nv_bfloat162 p = __halves2bfloat162(a, b);
    return *(uint32_t*)&p;
}
__device__ __forceinline__ void split4(float4 v, uint2& hh, uint2& ll) {
    __nv_bfloat16 h0, h1, h2, h3, l0, l1, l2, l3;
    bsplit(v.x, h0, l0); bsplit(v.y, h1, l1);
    bsplit(v.z, h2, l2); bsplit(v.w, h3, l3);
    hh = make_uint2(bpack(h0, h1), bpack(h2, h3));
    ll = make_uint2(bpack(l0, l1), bpack(l2, l3));
}
// pack 2 floats: hi pair and lo pair
__device__ __forceinline__ void packhl(float a, float b, uint32_t& hh, uint32_t& ll) {
    __nv_bfloat16 ha, la, hb, lb;
    bsplit(a, ha, la); bsplit(b, hb, lb);
    hh = bpack(ha, hb); ll = bpack(la, lb);
}

// warp compute for one 64-K chunk (gemm/scores kernels)
template <bool BKN>
__device__ __forceinline__ void mma_chunk(uint32_t ahB, uint32_t alB,
                                          uint32_t bhB, uint32_t blB,
                                          int wm, int wn, int lane,
                                          float acc[4][4][4]) {
#pragma unroll
    for (int ks = 0; ks < 4; ks++) {
        uint32_t bh[4][2], bl[4][2];
#pragma unroll
        for (int ni = 0; ni < 4; ni++) {
            uint32_t off;
            if (BKN)
                off = ((uint32_t)(ks * 16 + (lane & 7) + ((lane >> 3) & 1) * 8) * PB
                       + wn * 32 + ni * 8) * 2;
            else
                off = ((uint32_t)(wn * 32 + ni * 8 + (lane & 7)) * PA
                       + ks * 16 + ((lane >> 3) & 1) * 8) * 2;
            if (BKN) { ldmx2t(bh[ni], bhB + off); ldmx2t(bl[ni], blB + off); }
            else     { ldmx2 (bh[ni], bhB + off); ldmx2 (bl[ni], blB + off); }
        }
        uint32_t a[4][4];
        uint32_t aoff[4];
#pragma unroll
        for (int mi = 0; mi < 4; mi++) {
            aoff[mi] = ((uint32_t)(wm * 64 + mi * 16 + (lane & 15)) * PA
                        + ks * 16 + ((lane >> 4) << 3)) * 2;
            ldmx4(a[mi], ahB + aoff[mi]);
        }
#pragma unroll
        for (int mi = 0; mi < 4; mi++)
#pragma unroll
            for (int ni = 0; ni < 4; ni++) {
                mma16816(acc[mi][ni], a[mi], bh[ni]);
                mma16816(acc[mi][ni], a[mi], bl[ni]);
            }
#pragma unroll
        for (int mi = 0; mi < 4; mi++) ldmx4(a[mi], alB + aoff[mi]);
#pragma unroll
        for (int mi = 0; mi < 4; mi++)
#pragma unroll
            for (int ni = 0; ni < 4; ni++) mma16816(acc[mi][ni], a[mi], bh[ni]);
    }
}

#define GEMM_SMEM  (128 * PA * 2 * 2 + 64 * PB * 2 * 2)
#define SCORE_SMEM (128 * PA * 2 * 4)
#define ATTN2_SMEM (6 * 128 * PQ * 2)

// ---------------- bf16x3 mma GEMM ----------------
__device__ __forceinline__ void gemm_mma_body(const float* __restrict__ A,
                                              const float* __restrict__ Bm,
                                              float* __restrict__ C, int nch) {
    extern __shared__ char dsm[];
    char* Ah = dsm;
    char* Al = Ah + 128 * PA * 2;
    char* Bh = Al + 128 * PA * 2;
    char* Bl = Bh + 64 * PB * 2;
    uint32_t ahB = smem_u32(Ah), alB = smem_u32(Al);
    uint32_t bhB = smem_u32(Bh), blB = smem_u32(Bl);
    int tid = threadIdx.x;
    int wid = tid >> 5, lane = tid & 31;
    int wm = wid >> 2, wn = wid & 3;
    int crow = blockIdx.y * 128, ccol = blockIdx.x * 128;

    float acc[4][4][4];
#pragma unroll
    for (int mi = 0; mi < 4; mi++)
#pragma unroll
        for (int ni = 0; ni < 4; ni++)
#pragma unroll
            for (int e = 0; e < 4; e++) acc[mi][ni][e] = 0.f;

    for (int ch = 0; ch < nch; ch++) {
        int k0 = ch * 64;
        __syncthreads();
#pragma unroll
        for (int i = 0; i < 8; i++) {
            int idx = tid + i * 256;
            int row = idx >> 4, c4 = (idx & 15) * 4;
            float4 v = *(const float4*)&A[(size_t)(crow + row) * HID + k0 + c4];
            uint2 hh, ll;
            split4(v, hh, ll);
            *(uint2*)(Ah + ((uint32_t)row * PA + c4) * 2) = hh;
            *(uint2*)(Al + ((uint32_t)row * PA + c4) * 2) = ll;
        }
#pragma unroll
        for (int i = 0; i < 8; i++) {
            int idx = tid + i * 256;
            int kr = idx >> 5, n4 = (idx & 31) * 4;
            float4 v = *(const float4*)&Bm[(size_t)(k0 + kr) * HID + ccol + n4];
            uint2 hh, ll;
            split4(v, hh, ll);
            *(uint2*)(Bh + ((uint32_t)kr * PB + n4) * 2) = hh;
            *(uint2*)(Bl + ((uint32_t)kr * PB + n4) * 2) = ll;
        }
        __syncthreads();
        mma_chunk<true>(ahB, alB, bhB, blB, wm, wn, lane, acc);
    }

    int quad = lane >> 2, qq = lane & 3;
#pragma unroll
    for (int mi = 0; mi < 4; mi++)
#pragma unroll
        for (int ni = 0; ni < 4; ni++) {
            int r = crow + wm * 64 + mi * 16 + quad;
            int c = ccol + wn * 32 + ni * 8 + qq * 2;
            *(float2*)&C[(size_t)r * HID + c] = make_float2(acc[mi][ni][0], acc[mi][ni][1]);
            *(float2*)&C[(size_t)(r + 8) * HID + c] = make_float2(acc[mi][ni][2], acc[mi][ni][3]);
        }
}

__global__ __launch_bounds__(256) void qkv_mma_kernel(const float* __restrict__ x,
                                                      const float* __restrict__ wq,
                                                      const float* __restrict__ wk,
                                                      const float* __restrict__ wv) {
    const float* B = blockIdx.z == 0 ? wq : (blockIdx.z == 1 ? wk : wv);
    float* C = blockIdx.z == 0 ? g_q : (blockIdx.z == 1 ? g_k : g_v);
    gemm_mma_body(x, B, C, 16);
}

__global__ __launch_bounds__(256) void out_mma_kernel(const float* __restrict__ wo,
                                                      float* __restrict__ out) {
    gemm_mma_body(g_ao, wo, out, 16);
}

// ---------------- scores: bf16x3 mma Q@K^T + fused row-stat partials ----------------
__global__ __launch_bounds__(256) void scores_mma_kernel() {
    extern __shared__ char dsm[];
    char* Ah = dsm;
    char* Al = Ah + 128 * PA * 2;
    char* Bh = Al + 128 * PA * 2;
    char* Bl = Bh + 128 * PA * 2;
    uint32_t ahB = smem_u32(Ah), alB = smem_u32(Al);
    uint32_t bhB = smem_u32(Bh), blB = smem_u32(Bl);
    int tid = threadIdx.x;
    int wid = tid >> 5, lane = tid & 31;
    int wm = wid >> 2, wn = wid & 3;
    int h = blockIdx.z, q0 = blockIdx.y * 128, k0 = blockIdx.x * 128;
    const float* Aq = g_q + h * D;
    const float* Bk = g_k + h * D;

#pragma unroll
    for (int i = 0; i < 8; i++) {
        int idx = tid + i * 256;
        int row = idx >> 4, c4 = (idx & 15) * 4;
        uint32_t so = ((uint32_t)row * PA + c4) * 2;
        uint2 hh, ll;
        split4(*(const float4*)&Aq[(size_t)(q0 + row) * HID + c4], hh, ll);
        *(uint2*)(Ah + so) = hh;
        *(uint2*)(Al + so) = ll;
        split4(*(const float4*)&Bk[(size_t)(k0 + row) * HID + c4], hh, ll);
        *(uint2*)(Bh + so) = hh;
        *(uint2*)(Bl + so) = ll;
    }
    __syncthreads();

    float acc[4][4][4];
#pragma unroll
    for (int mi = 0; mi < 4; mi++)
#pragma unroll
        for (int ni = 0; ni < 4; ni++)
#pragma unroll
            for (int e = 0; e < 4; e++) acc[mi][ni][e] = 0.f;

    mma_chunk<false>(ahB, alB, bhB, blB, wm, wn, lane, acc);

#pragma unroll
    for (int mi = 0; mi < 4; mi++)
#pragma unroll
        for (int ni = 0; ni < 4; ni++)
#pragma unroll
            for (int e = 0; e < 4; e++) acc[mi][ni][e] *= SCALE;

    float* sc = g_scores + (size_t)h * S * S;
    int quad = lane >> 2, qq = lane & 3;
#pragma unroll
    for (int mi = 0; mi < 4; mi++)
#pragma unroll
        for (int ni = 0; ni < 4; ni++) {
            int r = q0 + wm * 64 + mi * 16 + quad;
            int c = k0 + wn * 32 + ni * 8 + qq * 2;
            *(float2*)&sc[(size_t)r * S + c] = make_float2(acc[mi][ni][0], acc[mi][ni][1]);
            *(float2*)&sc[(size_t)(r + 8) * S + c] = make_float2(acc[mi][ni][2], acc[mi][ni][3]);
        }

    int tile = blockIdx.x * 4 + wn;
#pragma unroll
    for (int mi = 0; mi < 4; mi++) {
        float m0 = -1e30f, m1 = -1e30f;
#pragma unroll
        for (int ni = 0; ni < 4; ni++) {
            m0 = fmaxf(m0, fmaxf(acc[mi][ni][0], acc[mi][ni][1]));
            m1 = fmaxf(m1, fmaxf(acc[mi][ni][2], acc[mi][ni][3]));
        }
        m0 = fmaxf(m0, __shfl_xor_sync(0xffffffffu, m0, 1));
        m0 = fmaxf(m0, __shfl_xor_sync(0xffffffffu, m0, 2));
        m1 = fmaxf(m1, __shfl_xor_sync(0xffffffffu, m1, 1));
        m1 = fmaxf(m1, __shfl_xor_sync(0xffffffffu, m1, 2));
        float z0 = 0.f, z1 = 0.f;
#pragma unroll
        for (int ni = 0; ni < 4; ni++) {
            z0 += __expf(acc[mi][ni][0] - m0) + __expf(acc[mi][ni][1] - m0);
            z1 += __expf(acc[mi][ni][2] - m1) + __expf(acc[mi][ni][3] - m1);
        }
        z0 += __shfl_xor_sync(0xffffffffu, z0, 1);
        z0 += __shfl_xor_sync(0xffffffffu, z0, 2);
        z1 += __shfl_xor_sync(0xffffffffu, z1, 1);
        z1 += __shfl_xor_sync(0xffffffffu, z1, 2);
        if (qq == 0) {
            int r = q0 + wm * 64 + mi * 16 + quad;
            size_t p0 = (size_t)(h * S + r) * NKT + tile;
            size_t p1 = (size_t)(h * S + r + 8) * NKT + tile;
            g_pm[p0] = m0; g_pz[p0] = z0;
            g_pm[p1] = m1; g_pz[p1] = z1;
        }
    }
}

// ---------------- combine partials (64 per row) ----------------
__global__ __launch_bounds__(256) void combine_kernel() {
    int row  = blockIdx.x * 8 + (threadIdx.x >> 5);
    int lane = threadIdx.x & 31;
    float pm0 = g_pm[(size_t)row * NKT + lane];
    float pz0 = g_pz[(size_t)row * NKT + lane];
    float pm1 = g_pm[(size_t)row * NKT + 32 + lane];
    float pz1 = g_pz[(size_t)row * NKT + 32 + lane];
    float m = fmaxf(pm0, pm1);
#pragma unroll
    for (int o = 16; o; o >>= 1) m = fmaxf(m, __shfl_xor_sync(0xffffffffu, m, o));
    float z = __expf(pm0 - m) * pz0 + __expf(pm1 - m) * pz1;
#pragma unroll
    for (int o = 16; o; o >>= 1) z += __shfl_xor_sync(0xffffffffu, z, o);
    if (lane == 0) {
        float rz = 1.0f / z;
        g_rowM[row] = m;
        g_rowZ[row] = rz;
        g_logZ[row] = __logf(z);
        g_maxa[row] = rz;
    }
}

// ---------------- fused entropy + influence ----------------
__global__ __launch_bounds__(256) void stats_kernel() {
    int h  = blockIdx.z;
    int q0 = blockIdx.y * 128;
    int k0 = blockIdx.x * 128;
    int tid = threadIdx.x;
    int wid = tid >> 5, lane = tid & 31;
    __shared__ float wcol[8][128];

    const float* sc = g_scores + (size_t)h * S * S;
    float c0 = 0.f, c1 = 0.f, c2 = 0.f, c3 = 0.f;

#pragma unroll 4
    for (int r = 0; r < 16; r++) {
        int row = q0 + wid * 16 + r;
        float m  = g_rowM[h * S + row];
        float rz = g_rowZ[h * S + row];
        float lz = g_logZ[h * S + row];
        float4 v = *(const float4*)&sc[(size_t)row * S + k0 + lane * 4];
        float s0 = v.x - m, s1 = v.y - m, s2 = v.z - m, s3 = v.w - m;
        float p0 = __expf(s0) * rz, p1 = __expf(s1) * rz;
        float p2 = __expf(s2) * rz, p3 = __expf(s3) * rz;
        c0 += p0; c1 += p1; c2 += p2; c3 += p3;
        float t0 = p0 * ((p0 >= 1e-8f) ? (s0 - lz) : LOG1EM8);
        float t1 = p1 * ((p1 >= 1e-8f) ? (s1 - lz) : LOG1EM8);
        float t2 = p2 * ((p2 >= 1e-8f) ? (s2 - lz) : LOG1EM8);
        float t3 = p3 * ((p3 >= 1e-8f) ? (s3 - lz) : LOG1EM8);
        float e = t0 + t1 + t2 + t3;
#pragma unroll
        for (int o = 16; o; o >>= 1) e += __shfl_xor_sync(0xffffffffu, e, o);
        if (lane == 0) atomicAdd(&g_ent[h * S + row], e);
    }
    *(float4*)&wcol[wid][lane * 4] = make_float4(c0, c1, c2, c3);
    __syncthreads();
    if (tid < 128) {
        float s = 0.f;
#pragma unroll
        for (int w = 0; w < 8; w++) s += wcol[w][tid];
        atomicAdd(&g_infl[h * S + k0 + tid], s);
    }
}

__global__ void importance_kernel() {
    int s = blockIdx.x * 256 + threadIdx.x;
    if (s >= S) return;
    float a = 0.f;
    for (int h = 0; h < H; h++)
        a += 0.4f * g_ent[h * S + s]
           + 0.3f * g_maxa[h * S + s] + 0.3f * g_infl[h * S + s];
    g_imp[s] = a * (1.0f / H);
}

__global__ void topk_kernel() {
    int i = blockIdx.x * 256 + threadIdx.x;
    if (i >= S) return;
    float vi = g_imp[i];
    int r = 0;
    for (int j = 0; j < S; j++) {
        float vj = g_imp[j];
        r += (vj > vi) || (vj == vi && j < i);
    }
    if (r < KHH) g_hhidx[r] = i;
}

// ---------------- norm-softmax-weighted 4:1 compression ----------------
__global__ __launch_bounds__(256) void compress_kernel() {
    int h = blockIdx.x;
    int which = blockIdx.y;
    const float* src = which ? g_v : g_k;
    float* dst = (which ? g_vcat : g_kcat) + ((size_t)h * KCPAD + KHH) * D;
    __shared__ float w[S];
    __shared__ float gs[LCOMP];
    __shared__ float red[256];
    int tid = threadIdx.x;

    for (int s = tid; s < S; s += 256) {
        const float* rp = src + (size_t)s * HID + h * D;
        float a = 0.f;
#pragma unroll
        for (int dd = 0; dd < 64; dd += 4) {
            float4 xv = *(const float4*)&rp[dd];
            a += xv.x * xv.x + xv.y * xv.y + xv.z * xv.z + xv.w * xv.w;
        }
        w[s] = sqrtf(a);
    }
    __syncthreads();
    float lm = -1e30f;
    for (int s = tid; s < S; s += 256) lm = fmaxf(lm, w[s]);
    red[tid] = lm; __syncthreads();
    for (int o = 128; o; o >>= 1) { if (tid < o) red[tid] = fmaxf(red[tid], red[tid + o]); __syncthreads(); }
    float m = red[0]; __syncthreads();
    float lz = 0.f;
    for (int s = tid; s < S; s += 256) { float e = __expf(w[s] - m); w[s] = e; lz += e; }
    red[tid] = lz; __syncthreads();
    for (int o = 128; o; o >>= 1) { if (tid < o) red[tid] += red[tid + o]; __syncthreads(); }
    float rz = 1.0f / red[0]; __syncthreads();
    for (int s = tid; s < S; s += 256) w[s] *= rz;
    __syncthreads();
    for (int l = tid; l < LCOMP; l += 256)
        gs[l] = w[4 * l] + w[4 * l + 1] + w[4 * l + 2] + w[4 * l + 3];
    __syncthreads();
    for (int idx = tid; idx < LCOMP * D; idx += 256) {
        int l  = idx >> 6;
        int dd = idx & 63;
        const float* rp = src + (size_t)(4 * l) * HID + h * D + dd;
        float num = w[4 * l] * rp[0] + w[4 * l + 1] * rp[HID] +
                    w[4 * l + 2] * rp[2 * HID] + w[4 * l + 3] * rp[3 * HID];
        dst[(size_t)l * D + dd] = num / (gs[l] + 1e-8f);
    }
}

__global__ void gather_kernel() {
    int idx = blockIdx.x * 256 + threadIdx.x;
    if (idx >= H * KHH * D) return;
    int d = idx & 63;
    int i = (idx >> 6) % KHH;
    int h = idx / (KHH * D);
    int s = g_hhidx[i];
    g_kcat[((size_t)h * KCPAD + i) * D + d] = g_k[(size_t)s * HID + h * D + d];
    g_vcat[((size_t)h * KCPAD + i) * D + d] = g_v[(size_t)s * HID + h * D + d];
}

// ---------------- attn2 on tensor pipe: flash over 6 chunks of 128 keys ----------------
__global__ __launch_bounds__(256) void attn2_mma_kernel() {
    extern __shared__ char dsm[];
    char* Qh = dsm;                       // [128][PQ] bf16 (q rows, d cols)
    char* Ql = Qh + 128 * PQ * 2;
    char* Kh = Ql + 128 * PQ * 2;         // [128 keys][PQ d]
    char* Kl = Kh + 128 * PQ * 2;
    char* Vh = Kl + 128 * PQ * 2;         // [128 keys][PQ d]
    char* Vl = Vh + 128 * PQ * 2;
    uint32_t qhB = smem_u32(Qh), qlB = smem_u32(Ql);
    uint32_t khB = smem_u32(Kh), klB = smem_u32(Kl);
    uint32_t vhB = smem_u32(Vh), vlB = smem_u32(Vl);
    int tid = threadIdx.x;
    int wid = tid >> 5, lane = tid & 31;
    int quad = lane >> 2, qq = lane & 3;
    int h = blockIdx.y, q0 = blockIdx.x * 128;

    // stage Q (hi/lo) once
#pragma unroll
    for (int i = 0; i < 8; i++) {
        int idx = tid + i * 256;
        int row = idx >> 4, c4 = (idx & 15) * 4;
        uint2 hh, ll;
        split4(*(const float4*)&g_q[(size_t)(q0 + row) * HID + h * D + c4], hh, ll);
        *(uint2*)(Qh + ((uint32_t)row * PQ + c4) * 2) = hh;
        *(uint2*)(Ql + ((uint32_t)row * PQ + c4) * 2) = ll;
    }
    const float* kbase = g_kcat + (size_t)h * KCPAD * D;
    const float* vbase = g_vcat + (size_t)h * KCPAD * D;

    float oacc[8][4];
#pragma unroll
    for (int ni = 0; ni < 8; ni++)
#pragma unroll
        for (int e = 0; e < 4; e++) oacc[ni][e] = 0.f;
    float m_run0 = -1e30f, m_run1 = -1e30f, z_run0 = 0.f, z_run1 = 0.f;

    for (int kt = 0; kt < KCPAD; kt += 128) {
        __syncthreads();
        // stage K,V chunk (hi/lo)
#pragma unroll
        for (int i = 0; i < 8; i++) {
            int idx = tid + i * 256;
            int row = idx >> 4, c4 = (idx & 15) * 4;
            uint32_t so = ((uint32_t)row * PQ + c4) * 2;
            uint2 hh, ll;
            split4(*(const float4*)&kbase[(size_t)(kt + row) * D + c4], hh, ll);
            *(uint2*)(Kh + so) = hh;
            *(uint2*)(Kl + so) = ll;
            split4(*(const float4*)&vbase[(size_t)(kt + row) * D + c4], hh, ll);
            *(uint2*)(Vh + so) = hh;
            *(uint2*)(Vl + so) = ll;
        }
        __syncthreads();

        // Q frags for this warp's 16 rows
        uint32_t qfh[4][4], qfl[4][4];
#pragma unroll
        for (int ks = 0; ks < 4; ks++) {
            uint32_t aoff = ((uint32_t)(wid * 16 + (lane & 15)) * PQ
                             + ks * 16 + ((lane >> 4) << 3)) * 2;
            ldmx4(qfh[ks], qhB + aoff);
            ldmx4(qfl[ks], qlB + aoff);
        }

        // S = Q @ K^T  (16 x 128)
        float sacc[16][4];
#pragma unroll
        for (int ni = 0; ni < 16; ni++)
#pragma unroll
            for (int e = 0; e < 4; e++) sacc[ni][e] = 0.f;
#pragma unroll
        for (int ks = 0; ks < 4; ks++) {
#pragma unroll
            for (int nj = 0; nj < 8; nj++) {
                // B [n][k] non-trans ldmx4: 2 n8 frags
                uint32_t part = lane >> 3;
                uint32_t boff = ((uint32_t)(nj * 16 + (part >> 1) * 8 + (lane & 7)) * PQ
                                 + ks * 16 + (part & 1) * 8) * 2;
                uint32_t bh[4], bl[4];
                ldmx4(bh, khB + boff);
                ldmx4(bl, klB + boff);
                mma16816(sacc[nj * 2],     qfh[ks], bh);
                mma16816(sacc[nj * 2],     qfh[ks], bl);
                mma16816(sacc[nj * 2],     qfl[ks], bh);
                mma16816(sacc[nj * 2 + 1], qfh[ks], bh + 2);
                mma16816(sacc[nj * 2 + 1], qfh[ks], bl + 2);
                mma16816(sacc[nj * 2 + 1], qfl[ks], bh + 2);
            }
        }

        // scale + mask
#pragma unroll
        for (int ni = 0; ni < 16; ni++) {
            int cg = kt + ni * 8 + qq * 2;
            bool ok0 = cg < KC, ok1 = (cg + 1) < KC;
            sacc[ni][0] = ok0 ? sacc[ni][0] * SCALE : -1e30f;
            sacc[ni][1] = ok1 ? sacc[ni][1] * SCALE : -1e30f;
            sacc[ni][2] = ok0 ? sacc[ni][2] * SCALE : -1e30f;
            sacc[ni][3] = ok1 ? sacc[ni][3] * SCALE : -1e30f;
        }
        // online softmax (rows quad, quad+8)
        float cm0 = -1e30f, cm1 = -1e30f;
#pragma unroll
        for (int ni = 0; ni < 16; ni++) {
            cm0 = fmaxf(cm0, fmaxf(sacc[ni][0], sacc[ni][1]));
            cm1 = fmaxf(cm1, fmaxf(sacc[ni][2], sacc[ni][3]));
        }
        cm0 = fmaxf(cm0, __shfl_xor_sync(0xffffffffu, cm0, 1));
        cm0 = fmaxf(cm0, __shfl_xor_sync(0xffffffffu, cm0, 2));
        cm1 = fmaxf(cm1, __shfl_xor_sync(0xffffffffu, cm1, 1));
        cm1 = fmaxf(cm1, __shfl_xor_sync(0xffffffffu, cm1, 2));
        float mn0 = fmaxf(m_run0, cm0), mn1 = fmaxf(m_run1, cm1);
        float fac0 = __expf(m_run0 - mn0), fac1 = __expf(m_run1 - mn1);
        m_run0 = mn0; m_run1 = mn1;
        float zs0 = 0.f, zs1 = 0.f;
#pragma unroll
        for (int ni = 0; ni < 16; ni++) {
            sacc[ni][0] = __expf(sacc[ni][0] - mn0);
            sacc[ni][1] = __expf(sacc[ni][1] - mn0);
            sacc[ni][2] = __expf(sacc[ni][2] - mn1);
            sacc[ni][3] = __expf(sacc[ni][3] - mn1);
            zs0 += sacc[ni][0] + sacc[ni][1];
            zs1 += sacc[ni][2] + sacc[ni][3];
        }
        zs0 += __shfl_xor_sync(0xffffffffu, zs0, 1);
        zs0 += __shfl_xor_sync(0xffffffffu, zs0, 2);
        zs1 += __shfl_xor_sync(0xffffffffu, zs1, 1);
        zs1 += __shfl_xor_sync(0xffffffffu, zs1, 2);
        z_run0 = z_run0 * fac0 + zs0;
        z_run1 = z_run1 * fac1 + zs1;
#pragma unroll
        for (int ni = 0; ni < 8; ni++) {
            oacc[ni][0] *= fac0; oacc[ni][1] *= fac0;
            oacc[ni][2] *= fac1; oacc[ni][3] *= fac1;
        }

        // P @ V : P frags from C frags in registers (hi/lo)
#pragma unroll
        for (int ks = 0; ks < 8; ks++) {
            uint32_t ph[4], pl[4];
            packhl(sacc[2 * ks][0],     sacc[2 * ks][1],     ph[0], pl[0]);
            packhl(sacc[2 * ks][2],     sacc[2 * ks][3],     ph[1], pl[1]);
            packhl(sacc[2 * ks + 1][0], sacc[2 * ks + 1][1], ph[2], pl[2]);
            packhl(sacc[2 * ks + 1][2], sacc[2 * ks + 1][3], ph[3], pl[3]);
#pragma unroll
            for (int nj = 0; nj < 4; nj++) {
                // B [k][n] trans ldmx4: 2 n8 frags
                uint32_t part = lane >> 3;
                uint32_t boff = ((uint32_t)(ks * 16 + (part & 1) * 8 + (lane & 7)) * PQ
                                 + nj * 16 + (part >> 1) * 8) * 2;
                uint32_t vh[4], vl[4];
                ldmx4t(vh, vhB + boff);
                ldmx4t(vl, vlB + boff);
                mma16816(oacc[nj * 2],     ph, vh);
                mma16816(oacc[nj * 2],     ph, vl);
                mma16816(oacc[nj * 2],     pl, vh);
                mma16816(oacc[nj * 2 + 1], ph, vh + 2);
                mma16816(oacc[nj * 2 + 1], ph, vl + 2);
                mma16816(oacc[nj * 2 + 1], pl, vh + 2);
            }
        }
    }

    float rz0 = 1.0f / z_run0, rz1 = 1.0f / z_run1;
    int r0 = q0 + wid * 16 + quad;
#pragma unroll
    for (int ni = 0; ni < 8; ni++) {
        int c = h * D + ni * 8 + qq * 2;
        *(float2*)&g_ao[(size_t)r0 * HID + c] =
            make_float2(oacc[ni][0] * rz0, oacc[ni][1] * rz0);
        *(float2*)&g_ao[(size_t)(r0 + 8) * HID + c] =
            make_float2(oacc[ni][2] * rz1, oacc[ni][3] * rz1);
    }
}

// ---------------- host ----------------
extern "C" void kernel_launch(void* const* d_in, const int* in_sizes, int n_in,
                              void* d_out, int out_size) {
    const float* x  = (const float*)d_in[0];
    const float* wq = (const float*)d_in[1];
    const float* wk = (const float*)d_in[2];
    const float* wv = (const float*)d_in[3];
    const float* wo = (const float*)d_in[4];
    float* out = (float*)d_out;

    static bool init_done = false;
    static void* ent_addr = nullptr;
    static void* infl_addr = nullptr;
    static void* kcat_addr = nullptr;
    static void* vcat_addr = nullptr;
    if (!init_done) {
        cudaFuncSetAttribute(attn2_mma_kernel,
                             cudaFuncAttributeMaxDynamicSharedMemorySize, ATTN2_SMEM);
        cudaFuncSetAttribute(qkv_mma_kernel,
                             cudaFuncAttributeMaxDynamicSharedMemorySize, GEMM_SMEM);
        cudaFuncSetAttribute(out_mma_kernel,
                             cudaFuncAttributeMaxDynamicSharedMemorySize, GEMM_SMEM);
        cudaFuncSetAttribute(scores_mma_kernel,
                             cudaFuncAttributeMaxDynamicSharedMemorySize, SCORE_SMEM);
        cudaGetSymbolAddress(&ent_addr, g_ent);
        cudaGetSymbolAddress(&infl_addr, g_infl);
        cudaGetSymbolAddress(&kcat_addr, g_kcat);
        cudaGetSymbolAddress(&vcat_addr, g_vcat);
        init_done = true;
    }

    cudaMemsetAsync(ent_addr, 0, H * S * sizeof(float));
    cudaMemsetAsync(infl_addr, 0, H * S * sizeof(float));
    cudaMemsetAsync(kcat_addr, 0, (size_t)H * KCPAD * D * sizeof(float));
    cudaMemsetAsync(vcat_addr, 0, (size_t)H * KCPAD * D * sizeof(float));

    qkv_mma_kernel<<<dim3(8, 16, 3), 256, GEMM_SMEM>>>(x, wq, wk, wv);
    scores_mma_kernel<<<dim3(16, 16, 16), 256, SCORE_SMEM>>>();
    combine_kernel<<<(H * S) / 8, 256>>>();
    stats_kernel<<<dim3(16, 16, 16), 256>>>();
    importance_kernel<<<8, 256>>>();
    topk_kernel<<<8, 256>>>();
    compress_kernel<<<dim3(16, 2), 256>>>();
    gather_kernel<<<(H * KHH * D + 255) / 256, 256>>>();
    attn2_mma_kernel<<<dim3(S / 128, H), 256, ATTN2_SMEM>>>();
    out_mma_kernel<<<dim3(8, 16), 256, GEMM_SMEM>>>(wo, out);
}